// round 1
// baseline (speedup 1.0000x reference)
#include <cuda_runtime.h>
#include <math_constants.h>

#define NN 1024
#define DD 64
#define HP 64
#define HA 256
#define TJ 16
#define NTHREADS 256

// ---------------- static scratch (no allocs allowed) ----------------
__device__ float g_q[NN * DD];
__device__ float g_k[NN * DD];
__device__ float g_v[NN * DD];
__device__ float g_posW[NN * HP];

// ---------------- precompute: q,k,v = x@W*, posW = pos@pW1 ----------------
__global__ __launch_bounds__(NTHREADS) void precompute_kernel(
    const float* __restrict__ x, const float* __restrict__ pos,
    const float* __restrict__ Wq, const float* __restrict__ Wk,
    const float* __restrict__ Wv, const float* __restrict__ pW1)
{
    int row = blockIdx.x * 4 + (threadIdx.x >> 6);
    int d   = threadIdx.x & 63;
    const float* xr = x + row * DD;
    float aq = 0.f, ak = 0.f, av = 0.f;
#pragma unroll
    for (int c = 0; c < DD; c++) {
        float xv = xr[c];
        aq = fmaf(xv, Wq[c * DD + d], aq);
        ak = fmaf(xv, Wk[c * DD + d], ak);
        av = fmaf(xv, Wv[c * DD + d], av);
    }
    g_q[row * DD + d] = aq;
    g_k[row * DD + d] = ak;
    g_v[row * DD + d] = av;
    g_posW[row * HP + d] = fmaf(pos[row * 2 + 0], pW1[0 * HP + d],
                                pos[row * 2 + 1] * pW1[1 * HP + d]);
}

// ---------------- fused main kernel: one CTA per query index i ----------------
struct __align__(16) Smem {
    float aW1[DD * HA];       // [d][hh]
    float aW2[HA * DD];       // [hh][d]
    float pW2[HP * DD];       // [h][d]
    float pb1[HP];
    float pb2[DD];
    float ab1[HA];
    float ab2[DD];
    float qi[DD];
    float posWi[HP];
    float ktile[TJ * DD];
    float vtile[TJ * DD];
    float posWj[TJ * HP];
    float h1[TJ * HP];
    float tt[TJ * DD];        // qk_rel + rpe (pre-activation input)
    float h2[TJ * HA];
    float part[4][TJ * DD];   // per-hh-quarter sim partials (reused as merge scratch)
};

__global__ __launch_bounds__(NTHREADS, 1) void pt_layer_kernel(
    const float* __restrict__ pb1, const float* __restrict__ pW2,
    const float* __restrict__ pb2, const float* __restrict__ aW1,
    const float* __restrict__ ab1, const float* __restrict__ aW2,
    const float* __restrict__ ab2, float* __restrict__ out)
{
    extern __shared__ float smem_raw[];
    Smem* s = reinterpret_cast<Smem*>(smem_raw);
    const int tid = threadIdx.x;
    const int i   = blockIdx.x;

    // ---- stage weights + biases + per-i vectors into smem ----
    for (int idx = tid; idx < DD * HA; idx += NTHREADS) s->aW1[idx] = aW1[idx];
    for (int idx = tid; idx < HA * DD; idx += NTHREADS) s->aW2[idx] = aW2[idx];
    for (int idx = tid; idx < HP * DD; idx += NTHREADS) s->pW2[idx] = pW2[idx];
    if (tid < HP) s->pb1[tid] = pb1[tid];
    if (tid < DD) s->pb2[tid] = pb2[tid];
    s->ab1[tid] = ab1[tid];                 // HA == NTHREADS
    if (tid < DD) s->ab2[tid] = ab2[tid];
    if (tid < DD) s->qi[tid] = g_q[i * DD + tid];
    if (tid < HP) s->posWi[tid] = g_posW[i * HP + tid];
    __syncthreads();

    // online-softmax state: thread owns (qq = tid>>6 subset of jj, d = tid&63)
    const int d_own  = tid & 63;
    const int qq_own = tid >> 6;
    const float qi_d = s->qi[d_own];
    float m = -CUDART_INF_F, lsum = 0.f, acc = 0.f;

    for (int j0 = 0; j0 < NN; j0 += TJ) {
        // ---- stage 0: load k / v / posW tiles (float4, 1 per thread each) ----
        {
            const float4* gk = reinterpret_cast<const float4*>(g_k + j0 * DD);
            const float4* gv = reinterpret_cast<const float4*>(g_v + j0 * DD);
            const float4* gp = reinterpret_cast<const float4*>(g_posW + j0 * HP);
            reinterpret_cast<float4*>(s->ktile)[tid] = gk[tid];
            reinterpret_cast<float4*>(s->vtile)[tid] = gv[tid];
            reinterpret_cast<float4*>(s->posWj)[tid] = gp[tid];
        }
        __syncthreads();

        // ---- stage 1a: h1[jj][h] = relu(posWi - posWj + pb1) ----
#pragma unroll
        for (int r = 0; r < 4; r++) {
            int o = tid + r * NTHREADS;
            int jj = o >> 6, h = o & 63;
            float v = s->posWi[h] - s->posWj[jj * HP + h] + s->pb1[h];
            s->h1[o] = fmaxf(v, 0.f);
        }
        __syncthreads();

        // ---- stage 1b: tt[jj][d] = (q_i - k_j) + h1 @ pW2 + pb2 ----
        {
            const int d  = tid & 63;
            const int jb = tid >> 6;
            float base = s->qi[d] + s->pb2[d];
            float a[4];
#pragma unroll
            for (int r = 0; r < 4; r++)
                a[r] = base - s->ktile[(jb + 4 * r) * DD + d];
#pragma unroll
            for (int h = 0; h < HP; h++) {
                float w = s->pW2[h * DD + d];
#pragma unroll
                for (int r = 0; r < 4; r++)
                    a[r] = fmaf(s->h1[(jb + 4 * r) * HP + h], w, a[r]);
            }
#pragma unroll
            for (int r = 0; r < 4; r++)
                s->tt[(jb + 4 * r) * DD + d] = a[r];
        }
        __syncthreads();

        // ---- stage 2: h2[jj][hh] = relu(tt @ aW1 + ab1), 4jj x 4hh blocking ----
        {
            const int hg = tid & 63;   // hh base = 4*hg
            const int jb = tid >> 6;   // jj base = 4*jb
            float a2[4][4];
#pragma unroll
            for (int a = 0; a < 4; a++)
#pragma unroll
                for (int b = 0; b < 4; b++) a2[a][b] = 0.f;
#pragma unroll
            for (int d = 0; d < DD; d++) {
                float4 w = *reinterpret_cast<const float4*>(s->aW1 + d * HA + 4 * hg);
                float t0 = s->tt[(4 * jb + 0) * DD + d];
                float t1 = s->tt[(4 * jb + 1) * DD + d];
                float t2 = s->tt[(4 * jb + 2) * DD + d];
                float t3 = s->tt[(4 * jb + 3) * DD + d];
                a2[0][0] = fmaf(t0, w.x, a2[0][0]); a2[0][1] = fmaf(t0, w.y, a2[0][1]);
                a2[0][2] = fmaf(t0, w.z, a2[0][2]); a2[0][3] = fmaf(t0, w.w, a2[0][3]);
                a2[1][0] = fmaf(t1, w.x, a2[1][0]); a2[1][1] = fmaf(t1, w.y, a2[1][1]);
                a2[1][2] = fmaf(t1, w.z, a2[1][2]); a2[1][3] = fmaf(t1, w.w, a2[1][3]);
                a2[2][0] = fmaf(t2, w.x, a2[2][0]); a2[2][1] = fmaf(t2, w.y, a2[2][1]);
                a2[2][2] = fmaf(t2, w.z, a2[2][2]); a2[2][3] = fmaf(t2, w.w, a2[2][3]);
                a2[3][0] = fmaf(t3, w.x, a2[3][0]); a2[3][1] = fmaf(t3, w.y, a2[3][1]);
                a2[3][2] = fmaf(t3, w.z, a2[3][2]); a2[3][3] = fmaf(t3, w.w, a2[3][3]);
            }
            float4 b = *reinterpret_cast<const float4*>(s->ab1 + 4 * hg);
#pragma unroll
            for (int jjq = 0; jjq < 4; jjq++) {
                float4 o;
                o.x = fmaxf(a2[jjq][0] + b.x, 0.f);
                o.y = fmaxf(a2[jjq][1] + b.y, 0.f);
                o.z = fmaxf(a2[jjq][2] + b.z, 0.f);
                o.w = fmaxf(a2[jjq][3] + b.w, 0.f);
                *reinterpret_cast<float4*>(s->h2 + (4 * jb + jjq) * HA + 4 * hg) = o;
            }
        }
        __syncthreads();

        // ---- stage 3: sim partials: part[q][jj][d] = h2[jj][hh in q-chunk] @ aW2 ----
        {
            const int q  = tid >> 6;          // hh chunk
            const int dg = tid & 15;          // d base = 4*dg
            const int jg = (tid >> 4) & 3;    // jj base = 4*jg
            float a3[4][4];
#pragma unroll
            for (int a = 0; a < 4; a++)
#pragma unroll
                for (int b = 0; b < 4; b++) a3[a][b] = 0.f;
            const int hh0 = q * 64;
#pragma unroll
            for (int hr = 0; hr < 64; hr++) {
                int hh = hh0 + hr;
                float4 w = *reinterpret_cast<const float4*>(s->aW2 + hh * DD + 4 * dg);
                float h0 = s->h2[(4 * jg + 0) * HA + hh];
                float h1v = s->h2[(4 * jg + 1) * HA + hh];
                float h2v = s->h2[(4 * jg + 2) * HA + hh];
                float h3v = s->h2[(4 * jg + 3) * HA + hh];
                a3[0][0] = fmaf(h0, w.x, a3[0][0]); a3[0][1] = fmaf(h0, w.y, a3[0][1]);
                a3[0][2] = fmaf(h0, w.z, a3[0][2]); a3[0][3] = fmaf(h0, w.w, a3[0][3]);
                a3[1][0] = fmaf(h1v, w.x, a3[1][0]); a3[1][1] = fmaf(h1v, w.y, a3[1][1]);
                a3[1][2] = fmaf(h1v, w.z, a3[1][2]); a3[1][3] = fmaf(h1v, w.w, a3[1][3]);
                a3[2][0] = fmaf(h2v, w.x, a3[2][0]); a3[2][1] = fmaf(h2v, w.y, a3[2][1]);
                a3[2][2] = fmaf(h2v, w.z, a3[2][2]); a3[2][3] = fmaf(h2v, w.w, a3[2][3]);
                a3[3][0] = fmaf(h3v, w.x, a3[3][0]); a3[3][1] = fmaf(h3v, w.y, a3[3][1]);
                a3[3][2] = fmaf(h3v, w.z, a3[3][2]); a3[3][3] = fmaf(h3v, w.w, a3[3][3]);
            }
#pragma unroll
            for (int jjq = 0; jjq < 4; jjq++) {
                float4 o;
                o.x = a3[jjq][0]; o.y = a3[jjq][1]; o.z = a3[jjq][2]; o.w = a3[jjq][3];
                *reinterpret_cast<float4*>(&s->part[q][(4 * jg + jjq) * DD + 4 * dg]) = o;
            }
        }
        __syncthreads();

        // ---- stage 4: online softmax update (thread owns qq subset of jj) ----
#pragma unroll
        for (int jq = 0; jq < 4; jq++) {
            int jj = 4 * qq_own + jq;
            int o = jj * DD + d_own;
            float sv = s->ab2[d_own] + s->part[0][o] + s->part[1][o]
                                     + s->part[2][o] + s->part[3][o];
            // vv = v_j + rpe = v_j + (tt - (q_i - k_j))
            float vv = s->vtile[o] + s->tt[o] - qi_d + s->ktile[o];
            float nm = fmaxf(m, sv);
            float scale = __expf(m - nm);     // exp(-inf)=0 on first iter
            float e = __expf(sv - nm);
            lsum = fmaf(lsum, scale, e);
            acc  = fmaf(acc, scale, e * vv);
            m = nm;
        }
        __syncthreads();
    }

    // ---- merge the 4 per-thread softmax partials per channel d ----
    s->part[0][tid] = m;
    s->part[1][tid] = lsum;
    s->part[2][tid] = acc;
    __syncthreads();
    if (tid < DD) {
        float M = s->part[0][tid];
#pragma unroll
        for (int q = 1; q < 4; q++) M = fmaxf(M, s->part[0][q * 64 + tid]);
        float L = 0.f, A = 0.f;
#pragma unroll
        for (int q = 0; q < 4; q++) {
            float w = __expf(s->part[0][q * 64 + tid] - M);
            L = fmaf(s->part[1][q * 64 + tid], w, L);
            A = fmaf(s->part[2][q * 64 + tid], w, A);
        }
        out[i * DD + tid] = A / L;
    }
}

// ---------------- launch ----------------
extern "C" void kernel_launch(void* const* d_in, const int* in_sizes, int n_in,
                              void* d_out, int out_size)
{
    (void)in_sizes; (void)n_in; (void)out_size;
    const float* x   = (const float*)d_in[0];
    const float* pos = (const float*)d_in[1];
    const float* Wq  = (const float*)d_in[2];
    const float* Wk  = (const float*)d_in[3];
    const float* Wv  = (const float*)d_in[4];
    const float* pW1 = (const float*)d_in[5];
    const float* pb1 = (const float*)d_in[6];
    const float* pW2 = (const float*)d_in[7];
    const float* pb2 = (const float*)d_in[8];
    const float* aW1 = (const float*)d_in[9];
    const float* ab1 = (const float*)d_in[10];
    const float* aW2 = (const float*)d_in[11];
    const float* ab2 = (const float*)d_in[12];
    float* out = (float*)d_out;

    static int smem_set = 0;
    size_t smem_bytes = sizeof(Smem);
    cudaFuncSetAttribute(pt_layer_kernel,
                         cudaFuncAttributeMaxDynamicSharedMemorySize,
                         (int)smem_bytes);
    (void)smem_set;

    precompute_kernel<<<NN / 4, NTHREADS>>>(x, pos, Wq, Wk, Wv, pW1);
    pt_layer_kernel<<<NN, NTHREADS, smem_bytes>>>(pb1, pW2, pb2, aW1, ab1, aW2, ab2, out);
}

// round 4
// speedup vs baseline: 1.6256x; 1.6256x over previous
#include <cuda_runtime.h>
#include <math_constants.h>

#define NN 1024
#define DD 64
#define HP 64
#define HA 256
#define TJ 16
#define NTHREADS 256

// ---------------- static scratch (no allocs allowed) ----------------
__device__ float g_q[NN * DD];
__device__ float g_k[NN * DD];
__device__ float g_v[NN * DD];
__device__ float g_posW[NN * HP];

// ---------------- precompute: q,k,v = x@W*, posW = pos@pW1 ----------------
__global__ __launch_bounds__(NTHREADS) void precompute_kernel(
    const float* __restrict__ x, const float* __restrict__ pos,
    const float* __restrict__ Wq, const float* __restrict__ Wk,
    const float* __restrict__ Wv, const float* __restrict__ pW1)
{
    int row = blockIdx.x * 4 + (threadIdx.x >> 6);
    int d   = threadIdx.x & 63;
    const float* xr = x + row * DD;
    float aq = 0.f, ak = 0.f, av = 0.f;
#pragma unroll
    for (int c = 0; c < DD; c++) {
        float xv = xr[c];
        aq = fmaf(xv, Wq[c * DD + d], aq);
        ak = fmaf(xv, Wk[c * DD + d], ak);
        av = fmaf(xv, Wv[c * DD + d], av);
    }
    g_q[row * DD + d] = aq;
    g_k[row * DD + d] = ak;
    g_v[row * DD + d] = av;
    g_posW[row * HP + d] = fmaf(pos[row * 2 + 0], pW1[0 * HP + d],
                                pos[row * 2 + 1] * pW1[1 * HP + d]);
}

// ---------------- fused main kernel: one CTA per query index i ----------------
struct __align__(16) Smem {
    float aW1[DD * HA];       // [d][hh]
    float aW2[HA * DD];       // [hh][d]
    float pW2[HP * DD];       // [h][d]
    float pb1[HP];
    float pb2[DD];
    float ab1[HA];
    float ab2[DD];
    float qi[DD];
    float posWi[HP];
    float ktile[TJ * DD];
    float vtile[TJ * DD];
    float posWj[TJ * HP];
    float h1[TJ * HP];
    float tt[TJ * DD];        // qk_rel + rpe (pre-activation input)
    float h2[TJ * HA];
    float part[4][TJ * DD];   // per-hh-quarter sim partials (reused as merge scratch)
};

__global__ __launch_bounds__(NTHREADS, 1) void pt_layer_kernel(
    const float* __restrict__ pb1, const float* __restrict__ pW2,
    const float* __restrict__ pb2, const float* __restrict__ aW1,
    const float* __restrict__ ab1, const float* __restrict__ aW2,
    const float* __restrict__ ab2, float* __restrict__ out)
{
    extern __shared__ float smem_raw[];
    Smem* s = reinterpret_cast<Smem*>(smem_raw);
    const int tid = threadIdx.x;
    const int i   = blockIdx.x;

    // ---- stage weights + biases + per-i vectors into smem ----
    for (int idx = tid; idx < DD * HA; idx += NTHREADS) s->aW1[idx] = aW1[idx];
    for (int idx = tid; idx < HA * DD; idx += NTHREADS) s->aW2[idx] = aW2[idx];
    for (int idx = tid; idx < HP * DD; idx += NTHREADS) s->pW2[idx] = pW2[idx];
    if (tid < HP) s->pb1[tid] = pb1[tid];
    if (tid < DD) s->pb2[tid] = pb2[tid];
    s->ab1[tid] = ab1[tid];                 // HA == NTHREADS
    if (tid < DD) s->ab2[tid] = ab2[tid];
    if (tid < DD) s->qi[tid] = g_q[i * DD + tid];
    if (tid < HP) s->posWi[tid] = g_posW[i * HP + tid];
    __syncthreads();

    // online-softmax state: thread owns (qq = tid>>6 subset of jj, d = tid&63)
    const int d_own  = tid & 63;
    const int qq_own = tid >> 6;
    const float qi_d = s->qi[d_own];
    float m = -CUDART_INF_F, lsum = 0.f, acc = 0.f;

    for (int j0 = 0; j0 < NN; j0 += TJ) {
        // ---- stage 0: load k / v / posW tiles (float4, 1 per thread each) ----
        {
            const float4* gk = reinterpret_cast<const float4*>(g_k + j0 * DD);
            const float4* gv = reinterpret_cast<const float4*>(g_v + j0 * DD);
            const float4* gp = reinterpret_cast<const float4*>(g_posW + j0 * HP);
            reinterpret_cast<float4*>(s->ktile)[tid] = gk[tid];
            reinterpret_cast<float4*>(s->vtile)[tid] = gv[tid];
            reinterpret_cast<float4*>(s->posWj)[tid] = gp[tid];
        }
        __syncthreads();

        // ---- stage 1a: h1[jj][h] = relu(posWi - posWj + pb1) ----
#pragma unroll
        for (int r = 0; r < 4; r++) {
            int o = tid + r * NTHREADS;
            int jj = o >> 6, h = o & 63;
            float v = s->posWi[h] - s->posWj[jj * HP + h] + s->pb1[h];
            s->h1[o] = fmaxf(v, 0.f);
        }
        __syncthreads();

        // ---- stage 1b: tt[jj][d] = (q_i - k_j) + h1 @ pW2 + pb2 ----
        {
            const int d  = tid & 63;
            const int jb = tid >> 6;
            float base = s->qi[d] + s->pb2[d];
            float a[4];
#pragma unroll
            for (int r = 0; r < 4; r++)
                a[r] = base - s->ktile[(jb + 4 * r) * DD + d];
#pragma unroll
            for (int h = 0; h < HP; h++) {
                float w = s->pW2[h * DD + d];
#pragma unroll
                for (int r = 0; r < 4; r++)
                    a[r] = fmaf(s->h1[(jb + 4 * r) * HP + h], w, a[r]);
            }
#pragma unroll
            for (int r = 0; r < 4; r++)
                s->tt[(jb + 4 * r) * DD + d] = a[r];
        }
        __syncthreads();

        // ---- stage 2: h2[jj][hh] = relu(tt @ aW1 + ab1), 4jj x 4hh blocking ----
        {
            const int hg = tid & 63;   // hh base = 4*hg
            const int jb = tid >> 6;   // jj base = 4*jb
            float a2[4][4];
#pragma unroll
            for (int a = 0; a < 4; a++)
#pragma unroll
                for (int b = 0; b < 4; b++) a2[a][b] = 0.f;
#pragma unroll
            for (int d = 0; d < DD; d++) {
                float4 w = *reinterpret_cast<const float4*>(s->aW1 + d * HA + 4 * hg);
                float t0 = s->tt[(4 * jb + 0) * DD + d];
                float t1 = s->tt[(4 * jb + 1) * DD + d];
                float t2 = s->tt[(4 * jb + 2) * DD + d];
                float t3 = s->tt[(4 * jb + 3) * DD + d];
                a2[0][0] = fmaf(t0, w.x, a2[0][0]); a2[0][1] = fmaf(t0, w.y, a2[0][1]);
                a2[0][2] = fmaf(t0, w.z, a2[0][2]); a2[0][3] = fmaf(t0, w.w, a2[0][3]);
                a2[1][0] = fmaf(t1, w.x, a2[1][0]); a2[1][1] = fmaf(t1, w.y, a2[1][1]);
                a2[1][2] = fmaf(t1, w.z, a2[1][2]); a2[1][3] = fmaf(t1, w.w, a2[1][3]);
                a2[2][0] = fmaf(t2, w.x, a2[2][0]); a2[2][1] = fmaf(t2, w.y, a2[2][1]);
                a2[2][2] = fmaf(t2, w.z, a2[2][2]); a2[2][3] = fmaf(t2, w.w, a2[2][3]);
                a2[3][0] = fmaf(t3, w.x, a2[3][0]); a2[3][1] = fmaf(t3, w.y, a2[3][1]);
                a2[3][2] = fmaf(t3, w.z, a2[3][2]); a2[3][3] = fmaf(t3, w.w, a2[3][3]);
            }
            float4 b = *reinterpret_cast<const float4*>(s->ab1 + 4 * hg);
#pragma unroll
            for (int jjq = 0; jjq < 4; jjq++) {
                float4 o;
                o.x = fmaxf(a2[jjq][0] + b.x, 0.f);
                o.y = fmaxf(a2[jjq][1] + b.y, 0.f);
                o.z = fmaxf(a2[jjq][2] + b.z, 0.f);
                o.w = fmaxf(a2[jjq][3] + b.w, 0.f);
                *reinterpret_cast<float4*>(s->h2 + (4 * jb + jjq) * HA + 4 * hg) = o;
            }
        }
        __syncthreads();

        // ---- stage 3: sim partials: part[q][jj][d] = h2[jj][hh in q-chunk] @ aW2 ----
        {
            const int q  = tid >> 6;          // hh chunk
            const int dg = tid & 15;          // d base = 4*dg
            const int jg = (tid >> 4) & 3;    // jj base = 4*jg
            float a3[4][4];
#pragma unroll
            for (int a = 0; a < 4; a++)
#pragma unroll
                for (int b = 0; b < 4; b++) a3[a][b] = 0.f;
            const int hh0 = q * 64;
#pragma unroll
            for (int hr = 0; hr < 64; hr++) {
                int hh = hh0 + hr;
                float4 w = *reinterpret_cast<const float4*>(s->aW2 + hh * DD + 4 * dg);
                float h0 = s->h2[(4 * jg + 0) * HA + hh];
                float h1v = s->h2[(4 * jg + 1) * HA + hh];
                float h2v = s->h2[(4 * jg + 2) * HA + hh];
                float h3v = s->h2[(4 * jg + 3) * HA + hh];
                a3[0][0] = fmaf(h0, w.x, a3[0][0]); a3[0][1] = fmaf(h0, w.y, a3[0][1]);
                a3[0][2] = fmaf(h0, w.z, a3[0][2]); a3[0][3] = fmaf(h0, w.w, a3[0][3]);
                a3[1][0] = fmaf(h1v, w.x, a3[1][0]); a3[1][1] = fmaf(h1v, w.y, a3[1][1]);
                a3[1][2] = fmaf(h1v, w.z, a3[1][2]); a3[1][3] = fmaf(h1v, w.w, a3[1][3]);
                a3[2][0] = fmaf(h2v, w.x, a3[2][0]); a3[2][1] = fmaf(h2v, w.y, a3[2][1]);
                a3[2][2] = fmaf(h2v, w.z, a3[2][2]); a3[2][3] = fmaf(h2v, w.w, a3[2][3]);
                a3[3][0] = fmaf(h3v, w.x, a3[3][0]); a3[3][1] = fmaf(h3v, w.y, a3[3][1]);
                a3[3][2] = fmaf(h3v, w.z, a3[3][2]); a3[3][3] = fmaf(h3v, w.w, a3[3][3]);
            }
#pragma unroll
            for (int jjq = 0; jjq < 4; jjq++) {
                float4 o;
                o.x = a3[jjq][0]; o.y = a3[jjq][1]; o.z = a3[jjq][2]; o.w = a3[jjq][3];
                *reinterpret_cast<float4*>(&s->part[q][(4 * jg + jjq) * DD + 4 * dg]) = o;
            }
        }
        __syncthreads();

        // ---- stage 4: online softmax update (thread owns qq subset of jj) ----
#pragma unroll
        for (int jq = 0; jq < 4; jq++) {
            int jj = 4 * qq_own + jq;
            int o = jj * DD + d_own;
            float sv = s->ab2[d_own] + s->part[0][o] + s->part[1][o]
                                     + s->part[2][o] + s->part[3][o];
            // vv = v_j + rpe = v_j + (tt - (q_i - k_j))
            float vv = s->vtile[o] + s->tt[o] - qi_d + s->ktile[o];
            float nm = fmaxf(m, sv);
            float scale = __expf(m - nm);     // exp(-inf)=0 on first iter
            float e = __expf(sv - nm);
            lsum = fmaf(lsum, scale, e);
            acc  = fmaf(acc, scale, e * vv);
            m = nm;
        }
        __syncthreads();
    }

    // ---- merge the 4 per-thread softmax partials per channel d ----
    s->part[0][tid] = m;
    s->part[1][tid] = lsum;
    s->part[2][tid] = acc;
    __syncthreads();
    if (tid < DD) {
        float M = s->part[0][tid];
#pragma unroll
        for (int q = 1; q < 4; q++) M = fmaxf(M, s->part[0][q * 64 + tid]);
        float L = 0.f, A = 0.f;
#pragma unroll
        for (int q = 0; q < 4; q++) {
            float w = __expf(s->part[0][q * 64 + tid] - M);
            L = fmaf(s->part[1][q * 64 + tid], w, L);
            A = fmaf(s->part[2][q * 64 + tid], w, A);
        }
        out[i * DD + tid] = A / L;
    }
}

// ---------------- launch ----------------
extern "C" void kernel_launch(void* const* d_in, const int* in_sizes, int n_in,
                              void* d_out, int out_size)
{
    (void)in_sizes; (void)n_in; (void)out_size;
    const float* x   = (const float*)d_in[0];
    const float* pos = (const float*)d_in[1];
    const float* Wq  = (const float*)d_in[2];
    const float* Wk  = (const float*)d_in[3];
    const float* Wv  = (const float*)d_in[4];
    const float* pW1 = (const float*)d_in[5];
    const float* pb1 = (const float*)d_in[6];
    const float* pW2 = (const float*)d_in[7];
    const float* pb2 = (const float*)d_in[8];
    const float* aW1 = (const float*)d_in[9];
    const float* ab1 = (const float*)d_in[10];
    const float* aW2 = (const float*)d_in[11];
    const float* ab2 = (const float*)d_in[12];
    float* out = (float*)d_out;

    static int smem_set = 0;
    size_t smem_bytes = sizeof(Smem);
    cudaFuncSetAttribute(pt_layer_kernel,
                         cudaFuncAttributeMaxDynamicSharedMemorySize,
                         (int)smem_bytes);
    (void)smem_set;

    precompute_kernel<<<NN / 4, NTHREADS>>>(x, pos, Wq, Wk, Wv, pW1);
    pt_layer_kernel<<<NN, NTHREADS, smem_bytes>>>(pb1, pW2, pb2, aW1, ab1, aW2, ab2, out);
}